// round 1
// baseline (speedup 1.0000x reference)
#include <cuda_runtime.h>
#include <math.h>
#include <stdint.h>

// ---------------------------------------------------------------------------
// GATNE forward, restructured:
//   k_wc    : build composite weight WC[840][200]
//   scanA/B : deterministic partition of rows by (indices[b] < NU)
//   k1      : neighbor gather+sum, per-type transform, attention -> featC rows
//   k_gemm  : out = featC @ WC  (launched twice: user-class rows use 2 k-tiles,
//             text-class rows use all 21)
//   k_norm  : row L2-normalize
//
// featC row layout (K = 840):
//   [0,32)   user features (idx < NU) else 0
//   [32,72)  agg (20 floats) placed at 32 + 20*type, other block 0
//   [72,840) text features (idx >= NU) else 0
// WC rows:   [0,32)=user_embed_trans, [32,72)=trans_weights[0..1], [72,840)=text_embed_trans
// ---------------------------------------------------------------------------

#define EMB       200
#define EMBU      20
#define DIMA      20
#define TEXT_DIM  768
#define USER_DIM  32
#define NSLOT     10
#define KTOT      840
#define SEG_AGG   32
#define SEG_TEXT  72

#define B_MAX     4096

// k1 config
#define GB1       16          // batch rows per CTA
#define SUT_LD    777         // padded row stride for transposed tweet U (conflict-free)
#define SUU_LD    33          // padded row stride for transposed user U
#define K1_SMEM_FLOATS (20*SUT_LD + 20*SUU_LD + TEXT_DIM + GB1*40)

// gemm config
#define GBM       16
#define GBK       40
#define GTM       4
#define GTN       5
#define GTHREADS  160         // 4 row-groups x 40 col-groups
#define ASTRIDE   20          // padded As row stride (16 used)
#define NTILES_ALL  (KTOT / GBK)   // 21
#define NTILES_USER 2              // covers k < 80 >= 72

// ------------------------- device scratch ----------------------------------
__device__ float g_featC[B_MAX * KTOT];
__device__ float g_WC[KTOT * EMB];
__device__ int   g_rowmap[B_MAX];
__device__ int   g_nuser;
__device__ int   g_pu[64];
__device__ int   g_pv[64];

// ------------------------- build WC ----------------------------------------
__global__ void k_wc(const float* __restrict__ user_embed,
                     const float* __restrict__ text_embed,
                     const float* __restrict__ trans_w)
{
    int i = blockIdx.x * blockDim.x + threadIdx.x;
    if (i >= KTOT * EMB) return;
    int k = i / EMB;
    int j = i - k * EMB;
    float v;
    if (k < SEG_AGG)        v = user_embed[k * EMB + j];
    else if (k < SEG_TEXT)  v = trans_w[(k - SEG_AGG) * EMB + j];   // [2,20,200] flat
    else                    v = text_embed[(k - SEG_TEXT) * EMB + j];
    g_WC[i] = v;
}

// ------------------------- partition scan ----------------------------------
__global__ void k_scanA(const int* __restrict__ indices, int B, int NU)
{
    int c = blockIdx.x;
    int tid = threadIdx.x;
    int b = c * 128 + tid;
    int f = (b < B && indices[b] < NU) ? 1 : 0;
    int v = (b < B) ? 1 : 0;
    for (int o = 16; o; o >>= 1) {
        f += __shfl_xor_sync(0xffffffffu, f, o);
        v += __shfl_xor_sync(0xffffffffu, v, o);
    }
    __shared__ int su[4], sv[4];
    if ((tid & 31) == 0) { su[tid >> 5] = f; sv[tid >> 5] = v; }
    __syncthreads();
    if (tid == 0) {
        g_pu[c] = su[0] + su[1] + su[2] + su[3];
        g_pv[c] = sv[0] + sv[1] + sv[2] + sv[3];
    }
}

__global__ void k_scanB(const int* __restrict__ indices, int B, int NU, int nblk)
{
    int c = blockIdx.x;
    int tid = threadIdx.x;
    int b = c * 128 + tid;
    int baseU = 0, baseV = 0, totU = 0;
    for (int i = 0; i < nblk; i++) {
        int pu = g_pu[i], pv = g_pv[i];
        if (i < c) { baseU += pu; baseV += pv; }
        totU += pu;
    }
    int f = (b < B && indices[b] < NU) ? 1 : 0;
    // inclusive warp scan in thread order
    int x = f;
    int lane = tid & 31, w = tid >> 5;
    for (int o = 1; o < 32; o <<= 1) {
        int y = __shfl_up_sync(0xffffffffu, x, o);
        if (lane >= o) x += y;
    }
    __shared__ int ws[4];
    if (lane == 31) ws[w] = x;
    __syncthreads();
    int wbase = 0;
    for (int i = 0; i < w; i++) wbase += ws[i];
    int excl = x + wbase - f;   // exclusive scan of user flags within block
    if (b < B) {
        int pos;
        if (f) {
            pos = baseU + excl;
        } else {
            int textBefore = (baseV - baseU) + (tid - excl);
            pos = totU + textBefore;
        }
        g_rowmap[pos] = b;
    }
    if (c == 0 && tid == 0) g_nuser = totU;
}

// ------------------------- kernel 1 ----------------------------------------
__global__ void k1_kernel(const int* __restrict__ train_types,
                          const int* __restrict__ node_neigh,
                          const int* __restrict__ indices,
                          const float* __restrict__ user_features,
                          const float* __restrict__ text_features,
                          const float* __restrict__ neigh_features,
                          const float* __restrict__ tweet_u,
                          const float* __restrict__ user_u,
                          const float* __restrict__ s1,
                          const float* __restrict__ s2,
                          int B, int NU)
{
    extern __shared__ float sm[];
    float* sUt  = sm;                       // [20][SUT_LD]  transposed tweet U
    float* sUu  = sUt + 20 * SUT_LD;        // [20][SUU_LD]  transposed user  U
    float* nsum = sUu + 20 * SUU_LD;        // [768]
    float* nte  = nsum + TEXT_DIM;          // [GB1][40]

    int tid  = threadIdx.x;
    int wid  = tid >> 5;
    int lane = tid & 31;
    int b0   = blockIdx.x * GB1;

    for (int t = 0; t < 2; t++) {
        // load U[t] transposed (coalesced global reads, conflict-free STS)
        for (int i = tid; i < TEXT_DIM * EMBU; i += 256) {
            int k = i / EMBU;
            int u = i - k * EMBU;
            sUt[u * SUT_LD + k] = tweet_u[(size_t)(t * TEXT_DIM + k) * EMBU + u];
        }
        for (int i = tid; i < USER_DIM * EMBU; i += 256) {
            int k = i / EMBU;
            int u = i - k * EMBU;
            sUu[u * SUU_LD + k] = user_u[(t * USER_DIM + k) * EMBU + u];
        }
        __syncthreads();

        for (int g = 0; g < GB1; g++) {
            int b = b0 + g;
            if (b >= B) break;                 // uniform across CTA
            int type  = train_types[b];
            bool tw   = (type == 1);
            int F     = tw ? TEXT_DIM : USER_DIM;
            const int* nn = node_neigh + ((size_t)b * 2 + t) * NSLOT;

            // gather + sum over 10 neighbor rows
            for (int k = tid; k < F; k += 256) {
                float acc = 0.f;
#pragma unroll
                for (int s = 0; s < NSLOT; s++)
                    acc += neigh_features[(size_t)nn[s] * TEXT_DIM + k];
                nsum[k] = acc;
            }
            __syncthreads();

            // nte[b][t][u] = nsum . U[t][:,u]
            const float* Us = tw ? sUt : sUu;
            int ld = tw ? SUT_LD : SUU_LD;
            for (int u = wid; u < EMBU; u += 8) {
                float acc = 0.f;
                for (int k = lane; k < F; k += 32)
                    acc += nsum[k] * Us[u * ld + k];
                for (int o = 16; o; o >>= 1)
                    acc += __shfl_xor_sync(0xffffffffu, acc, o);
                if (lane == 0) nte[g * 40 + t * EMBU + u] = acc;
            }
            __syncthreads();
        }
        __syncthreads();
    }

    // attention per row: one warp per g
    for (int g = wid; g < GB1; g += 8) {
        int b = b0 + g;
        if (b >= B) continue;
        int type = train_types[b];
        const float* S1 = s1 + type * (EMBU * DIMA);
        const float* S2 = s2 + type * DIMA;
        float sc[2];
#pragma unroll
        for (int t = 0; t < 2; t++) {
            float h = 0.f;
            if (lane < DIMA) {
#pragma unroll
                for (int u = 0; u < EMBU; u++)
                    h += nte[g * 40 + t * EMBU + u] * S1[u * DIMA + lane];
                h = tanhf(h) * S2[lane];
            }
            for (int o = 16; o; o >>= 1)
                h += __shfl_xor_sync(0xffffffffu, h, o);
            sc[t] = h;
        }
        float m  = fmaxf(sc[0], sc[1]);
        float e0 = expf(sc[0] - m);
        float e1 = expf(sc[1] - m);
        float inv = 1.f / (e0 + e1);
        float a0 = e0 * inv, a1 = e1 * inv;
        if (lane < EMBU) {
            float agg = a0 * nte[g * 40 + lane] + a1 * nte[g * 40 + EMBU + lane];
            nte[g * 40 + lane] = agg;
        }
    }
    __syncthreads();

    // write featC rows
    for (int g = 0; g < GB1; g++) {
        int b = b0 + g;
        if (b >= B) break;
        int idx  = indices[b];
        int type = train_types[b];
        bool isuser = (idx < NU);
        const float* uf = user_features + (size_t)(isuser ? idx : 0) * USER_DIM;
        const float* tf = text_features + (size_t)(isuser ? 0 : (idx - NU)) * TEXT_DIM;
        float* row = g_featC + (size_t)b * KTOT;
        for (int k = tid; k < KTOT; k += 256) {
            float v = 0.f;
            if (k < SEG_AGG) {
                if (isuser) v = uf[k];
            } else if (k < SEG_TEXT) {
                int kk = k - SEG_AGG;
                if ((kk / EMBU) == type) v = nte[g * 40 + (kk % EMBU)];
            } else {
                if (!isuser) v = tf[k - SEG_TEXT];
            }
            row[k] = v;
        }
    }
}

// ------------------------- GEMM --------------------------------------------
// 160 threads = 4 row-groups (GTM=4 rows each) x 40 col-groups (GTN=5 cols)
__global__ void k_gemm(float* __restrict__ out, int B, int which, int ntiles)
{
    __shared__ float As[GBK][ASTRIDE];
    __shared__ float Bs[GBK][EMB];
    __shared__ int   rows[GBM];

    int nuser = g_nuser;
    int base  = which ? nuser : 0;
    int cnt   = which ? (B - nuser) : nuser;
    int m0    = blockIdx.x * GBM;
    if (m0 >= cnt) return;

    int tid = threadIdx.x;
    if (tid < GBM) {
        int mm = m0 + tid;
        if (mm > cnt - 1) mm = cnt - 1;
        rows[tid] = g_rowmap[base + mm];
    }
    __syncthreads();

    float acc[GTM][GTN];
#pragma unroll
    for (int i = 0; i < GTM; i++)
#pragma unroll
        for (int j = 0; j < GTN; j++) acc[i][j] = 0.f;

    int rowid = tid / 40;        // 0..3
    int colid = tid - rowid * 40; // 0..39

    for (int kt = 0; kt < ntiles; kt++) {
        int k0 = kt * GBK;
        // A tile: 16 rows x 40 k  (640 elems)
        for (int i = tid; i < GBM * GBK; i += GTHREADS) {
            int m = i / GBK;
            int k = i - m * GBK;
            As[k][m] = g_featC[(size_t)rows[m] * KTOT + k0 + k];
        }
        // B tile: 40 x 200 (contiguous)
        for (int i = tid; i < GBK * EMB; i += GTHREADS) {
            ((float*)Bs)[i] = g_WC[k0 * EMB + i];
        }
        __syncthreads();

#pragma unroll 8
        for (int k = 0; k < GBK; k++) {
            const float4 av = *reinterpret_cast<const float4*>(&As[k][rowid * GTM]);
            float a[GTM] = {av.x, av.y, av.z, av.w};
            float bb[GTN];
#pragma unroll
            for (int j = 0; j < GTN; j++) bb[j] = Bs[k][colid * GTN + j];
#pragma unroll
            for (int i = 0; i < GTM; i++)
#pragma unroll
                for (int j = 0; j < GTN; j++)
                    acc[i][j] += a[i] * bb[j];
        }
        __syncthreads();
    }

#pragma unroll
    for (int i = 0; i < GTM; i++) {
        int m = m0 + rowid * GTM + i;
        if (m < cnt) {
            float* o = out + (size_t)rows[rowid * GTM + i] * EMB + colid * GTN;
#pragma unroll
            for (int j = 0; j < GTN; j++) o[j] = acc[i][j];
        }
    }
}

// ------------------------- normalize ---------------------------------------
__global__ void k_norm(float* __restrict__ out, int B)
{
    int b = blockIdx.x;
    if (b >= B) return;
    float* row = out + (size_t)b * EMB;
    int tid = threadIdx.x;
    float ss = 0.f;
    for (int j = tid; j < EMB; j += 64) {
        float x = row[j];
        ss += x * x;
    }
    for (int o = 16; o; o >>= 1) ss += __shfl_xor_sync(0xffffffffu, ss, o);
    __shared__ float s[2];
    if ((tid & 31) == 0) s[tid >> 5] = ss;
    __syncthreads();
    float tot = s[0] + s[1];
    float scale = 1.f / fmaxf(sqrtf(tot), 1e-12f);
    for (int j = tid; j < EMB; j += 64) row[j] *= scale;
}

// ------------------------- launch ------------------------------------------
extern "C" void kernel_launch(void* const* d_in, const int* in_sizes, int n_in,
                              void* d_out, int out_size)
{
    const int*   train_types   = (const int*)d_in[1];
    const int*   node_neigh    = (const int*)d_in[2];
    const int*   indices       = (const int*)d_in[3];
    const float* user_features = (const float*)d_in[4];
    const float* text_features = (const float*)d_in[5];
    const float* neigh_features= (const float*)d_in[6];
    const float* text_embed    = (const float*)d_in[7];
    const float* user_embed    = (const float*)d_in[8];
    const float* tweet_u       = (const float*)d_in[9];
    const float* user_u        = (const float*)d_in[10];
    const float* trans_w       = (const float*)d_in[11];
    const float* s1            = (const float*)d_in[12];
    const float* s2            = (const float*)d_in[13];

    int B  = in_sizes[3];
    int NU = in_sizes[4] / USER_DIM;
    float* out = (float*)d_out;

    const int k1_smem = K1_SMEM_FLOATS * (int)sizeof(float);
    cudaFuncSetAttribute(k1_kernel, cudaFuncAttributeMaxDynamicSharedMemorySize, k1_smem);

    k_wc<<<(KTOT * EMB + 255) / 256, 256>>>(user_embed, text_embed, trans_w);

    int nblk = (B + 127) / 128;
    k_scanA<<<nblk, 128>>>(indices, B, NU);
    k_scanB<<<nblk, 128>>>(indices, B, NU, nblk);

    k1_kernel<<<(B + GB1 - 1) / GB1, 256, k1_smem>>>(
        train_types, node_neigh, indices, user_features, text_features,
        neigh_features, tweet_u, user_u, s1, s2, B, NU);

    int ggrid = (B + GBM - 1) / GBM;
    k_gemm<<<ggrid, GTHREADS>>>(out, B, 0, NTILES_USER);
    k_gemm<<<ggrid, GTHREADS>>>(out, B, 1, NTILES_ALL);

    k_norm<<<B, 64>>>(out, B);
}

// round 6
// speedup vs baseline: 1.3501x; 1.3501x over previous
#include <cuda_runtime.h>
#include <math.h>
#include <stdint.h>

// ---------------------------------------------------------------------------
// GATNE forward v2:
//   k_scan  : single-CTA stable partition of rows by (indices[b] < NU)
//   k1      : parallel neighbor gather+sum (float4, MLP=10), per-type U
//             transform (warp-per-row), attention -> g_agg[B][40]
//   k_gemm2 : out = [userF | agg | textF] @ [userW ; transW ; textW],
//             A/B tiles read straight from source tensors, fused L2-normalize
// ---------------------------------------------------------------------------

#define EMB       200
#define EMBU      20
#define TEXT_DIM  768
#define USER_DIM  32
#define NSLOT     10
#define B_MAX     4096

// k1 config
#define GB        16
#define NSUM_LD   772          // padded nsum row stride (bank spread)

// gemm config
#define GBM       16
#define GBK       40
#define GTH       160

// ------------------------- device scratch ----------------------------------
__device__ int   g_rowmap[B_MAX];
__device__ int   g_nuser;
__device__ float g_agg[B_MAX * 40];

// ------------------------- partition scan (1 CTA) ---------------------------
__global__ void k_scan(const int* __restrict__ indices, int B, int NU)
{
    __shared__ int ws[32];
    int tid = threadIdx.x;                 // 0..1023
    int chunk = (B + 1023) / 1024;
    int b0 = tid * chunk;
    int cu = 0;
    for (int j = 0; j < chunk; j++) {
        int b = b0 + j;
        if (b < B && indices[b] < NU) cu++;
    }
    int lane = tid & 31, w = tid >> 5;
    int x = cu;
    for (int o = 1; o < 32; o <<= 1) {
        int y = __shfl_up_sync(0xffffffffu, x, o);
        if (lane >= o) x += y;
    }
    if (lane == 31) ws[w] = x;
    __syncthreads();
    int wbase = 0, totU = 0;
    for (int i = 0; i < 32; i++) {
        if (i < w) wbase += ws[i];
        totU += ws[i];
    }
    int u_run = (x - cu) + wbase;          // exclusive user count before chunk
    for (int j = 0; j < chunk; j++) {
        int b = b0 + j;
        if (b >= B) break;
        if (indices[b] < NU) g_rowmap[u_run++] = b;
        else                 g_rowmap[totU + (b - u_run)] = b;
    }
    if (tid == 0) g_nuser = totU;
}

// ------------------------- kernel 1 ----------------------------------------
__global__ __launch_bounds__(512, 1) void k1_kernel(
    const int*   __restrict__ train_types,
    const int*   __restrict__ node_neigh,
    const float* __restrict__ neigh_features,
    const float* __restrict__ tweet_u,
    const float* __restrict__ user_u,
    const float* __restrict__ s1,
    const float* __restrict__ s2,
    int B)
{
    extern __shared__ float sm[];
    float* sUt  = sm;                       // [2][768][20]
    float* sUu  = sUt + 2 * 768 * 20;       // [2][32][20]
    float* nsum = sUu + 2 * 32 * 20;        // [GB][NSUM_LD]
    float* nte  = nsum + GB * NSUM_LD;      // [GB][40]  (t=0 block, t=1 block)
    int*   snn  = (int*)(nte + GB * 40);    // [GB][2][NSLOT]
    int*   sty  = snn + GB * 2 * NSLOT;     // [GB]

    int tid  = threadIdx.x;
    int wid  = tid >> 5;
    int lane = tid & 31;
    int b0   = blockIdx.x * GB;

    // load both U tensors (coalesced float4)
    {
        const float4* src = (const float4*)tweet_u;
        float4* dst = (float4*)sUt;
        for (int i = tid; i < 2 * 768 * 20 / 4; i += 512) dst[i] = src[i];
        const float4* src2 = (const float4*)user_u;
        float4* dst2 = (float4*)sUu;
        for (int i = tid; i < 2 * 32 * 20 / 4; i += 512) dst2[i] = src2[i];
    }
    if (tid < GB * 2 * NSLOT) {
        int g = tid / (2 * NSLOT);
        int r = tid - g * (2 * NSLOT);
        int b = b0 + g; if (b >= B) b = B - 1;
        snn[tid] = node_neigh[(size_t)b * 2 * NSLOT + r];
    }
    if (tid < GB) { int b = b0 + tid; if (b >= B) b = B - 1; sty[tid] = train_types[b]; }
    __syncthreads();

    for (int t = 0; t < 2; t++) {
        // ---- gather+sum, all rows in parallel, float4, 10-way MLP ----
        for (int item = tid; item < GB * 192; item += 512) {
            int g  = item / 192;
            int k4 = item - g * 192;
            int F  = (sty[g] == 1) ? TEXT_DIM : USER_DIM;
            if (k4 * 4 < F) {
                const int* nn = snn + (g * 2 + t) * NSLOT;
                float4 acc = make_float4(0.f, 0.f, 0.f, 0.f);
#pragma unroll
                for (int s = 0; s < NSLOT; s++) {
                    const float4* p = (const float4*)(neigh_features +
                                      (size_t)nn[s] * TEXT_DIM) + k4;
                    float4 v = *p;
                    acc.x += v.x; acc.y += v.y; acc.z += v.z; acc.w += v.w;
                }
                *(float4*)(nsum + g * NSUM_LD + k4 * 4) = acc;
            }
        }
        __syncthreads();

        // ---- transform: warp w handles row w, lanes split k ----
        {
            int g = wid;
            int ty = sty[g];
            int F  = (ty == 1) ? TEXT_DIM : USER_DIM;
            const float* U = (ty == 1) ? (sUt + t * 768 * 20) : (sUu + t * 32 * 20);
            float acc[EMBU];
#pragma unroll
            for (int u = 0; u < EMBU; u++) acc[u] = 0.f;
            for (int k = lane; k < F; k += 32) {
                float nv = nsum[g * NSUM_LD + k];
                const float4* Urow = (const float4*)(U + k * EMBU);
#pragma unroll
                for (int q = 0; q < 5; q++) {
                    float4 uv = Urow[q];
                    acc[q * 4 + 0] += nv * uv.x;
                    acc[q * 4 + 1] += nv * uv.y;
                    acc[q * 4 + 2] += nv * uv.z;
                    acc[q * 4 + 3] += nv * uv.w;
                }
            }
#pragma unroll
            for (int u = 0; u < EMBU; u++) {
                float a = acc[u];
                for (int o = 16; o; o >>= 1) a += __shfl_xor_sync(0xffffffffu, a, o);
                if (lane == 0) nte[g * 40 + t * EMBU + u] = a;
            }
        }
        __syncthreads();
    }

    // ---- attention + agg write: warp per row ----
    {
        int g = wid;
        int b = b0 + g;
        if (b < B) {
            int ty = sty[g];
            const float* S1 = s1 + ty * (EMBU * EMBU);
            const float* S2 = s2 + ty * EMBU;
            float sc[2];
#pragma unroll
            for (int t = 0; t < 2; t++) {
                float h = 0.f;
                if (lane < EMBU) {
#pragma unroll
                    for (int u = 0; u < EMBU; u++)
                        h += nte[g * 40 + t * EMBU + u] * S1[u * EMBU + lane];
                    h = tanhf(h) * S2[lane];
                }
                for (int o = 16; o; o >>= 1) h += __shfl_xor_sync(0xffffffffu, h, o);
                sc[t] = h;
            }
            float m  = fmaxf(sc[0], sc[1]);
            float e0 = expf(sc[0] - m);
            float e1 = expf(sc[1] - m);
            float inv = 1.f / (e0 + e1);
            float a0 = e0 * inv, a1 = e1 * inv;
            for (int l = lane; l < 40; l += 32) {
                float v = 0.f;
                if ((l / EMBU) == ty) {
                    int u = l - (l / EMBU) * EMBU;
                    v = a0 * nte[g * 40 + u] + a1 * nte[g * 40 + EMBU + u];
                }
                g_agg[(size_t)b * 40 + l] = v;
            }
        }
    }
}

// ------------------------- GEMM + fused normalize ---------------------------
__global__ __launch_bounds__(GTH, 4) void k_gemm2(
    float* __restrict__ out,
    const int*   __restrict__ indices,
    const float* __restrict__ user_features,
    const float* __restrict__ text_features,
    const float* __restrict__ user_embed,
    const float* __restrict__ text_embed,
    const float* __restrict__ trans_w,
    int B, int NU)
{
    __shared__ float As[GBK][GBM + 4];
    __shared__ float Bs[GBK][EMB];
    __shared__ float sOut[GBM][EMB];
    __shared__ float snrm[GBM];
    __shared__ int   srow[GBM], sidx[GBM];

    int half = gridDim.x >> 1;
    int cls  = (blockIdx.x >= half) ? 1 : 0;
    int tile = cls ? (blockIdx.x - half) : blockIdx.x;
    int nuser = g_nuser;
    int base = cls ? nuser : 0;
    int cnt  = cls ? (B - nuser) : nuser;
    int m0   = tile * GBM;
    if (m0 >= cnt) return;

    int tid = threadIdx.x;
    if (tid < GBM) {
        int mm = m0 + tid; if (mm > cnt - 1) mm = cnt - 1;
        int b = g_rowmap[base + mm];
        srow[tid] = b;
        sidx[tid] = indices[b];
    }
    __syncthreads();

    int ntiles = cls ? 21 : 2;   // user rows: only k<80 is nonzero
    float acc[4][5];
#pragma unroll
    for (int i = 0; i < 4; i++)
#pragma unroll
        for (int j = 0; j < 5; j++) acc[i][j] = 0.f;

    int rowid = tid / 40;
    int colid = tid - rowid * 40;

    for (int kt = 0; kt < ntiles; kt++) {
        int k0 = kt * GBK;
        // A tile from source tensors
        for (int i = tid; i < GBM * GBK; i += GTH) {
            int m = i / GBK, k = i - m * GBK;
            int kk = k0 + k;
            int b = srow[m], idx = sidx[m];
            float v;
            if (kk < USER_DIM)
                v = (idx < NU) ? user_features[(size_t)idx * USER_DIM + kk] : 0.f;
            else if (kk < 72)
                v = g_agg[(size_t)b * 40 + (kk - USER_DIM)];
            else
                v = (idx < NU) ? 0.f
                               : text_features[(size_t)(idx - NU) * TEXT_DIM + (kk - 72)];
            As[k][m] = v;
        }
        // B tile from weight tensors (float2)
        for (int i = tid; i < GBK * (EMB / 2); i += GTH) {
            int k  = i / (EMB / 2);
            int j2 = i - k * (EMB / 2);
            int kk = k0 + k;
            const float* src;
            if (kk < USER_DIM)      src = user_embed + (size_t)kk * EMB;
            else if (kk < 72)       src = trans_w + (size_t)(kk - USER_DIM) * EMB;
            else                    src = text_embed + (size_t)(kk - 72) * EMB;
            *(float2*)&Bs[k][j2 * 2] = *(const float2*)(src + j2 * 2);
        }
        __syncthreads();

#pragma unroll 4
        for (int k = 0; k < GBK; k++) {
            float4 av = *(const float4*)&As[k][rowid * 4];
            float a[4] = {av.x, av.y, av.z, av.w};
            float bb[5];
#pragma unroll
            for (int j = 0; j < 5; j++) bb[j] = Bs[k][colid * 5 + j];
#pragma unroll
            for (int i = 0; i < 4; i++)
#pragma unroll
                for (int j = 0; j < 5; j++)
                    acc[i][j] += a[i] * bb[j];
        }
        __syncthreads();
    }

    // stash accumulators, compute row norms, scaled write
#pragma unroll
    for (int i = 0; i < 4; i++)
#pragma unroll
        for (int j = 0; j < 5; j++)
            sOut[rowid * 4 + i][colid * 5 + j] = acc[i][j];
    __syncthreads();

    int wid = tid >> 5, lane = tid & 31;
    for (int m = wid; m < GBM; m += 5) {
        float ss = 0.f;
        for (int j = lane; j < EMB; j += 32) { float x = sOut[m][j]; ss += x * x; }
        for (int o = 16; o; o >>= 1) ss += __shfl_xor_sync(0xffffffffu, ss, o);
        if (lane == 0) snrm[m] = 1.f / fmaxf(sqrtf(ss), 1e-12f);
    }
    __syncthreads();

    int mlim = cnt - m0; if (mlim > GBM) mlim = GBM;
    for (int i = tid; i < GBM * EMB; i += GTH) {
        int m = i / EMB, j = i - m * EMB;
        if (m < mlim)
            out[(size_t)srow[m] * EMB + j] = sOut[m][j] * snrm[m];
    }
}

// ------------------------- launch ------------------------------------------
extern "C" void kernel_launch(void* const* d_in, const int* in_sizes, int n_in,
                              void* d_out, int out_size)
{
    const int*   train_types    = (const int*)d_in[1];
    const int*   node_neigh     = (const int*)d_in[2];
    const int*   indices        = (const int*)d_in[3];
    const float* user_features  = (const float*)d_in[4];
    const float* text_features  = (const float*)d_in[5];
    const float* neigh_features = (const float*)d_in[6];
    const float* text_embed     = (const float*)d_in[7];
    const float* user_embed     = (const float*)d_in[8];
    const float* tweet_u        = (const float*)d_in[9];
    const float* user_u         = (const float*)d_in[10];
    const float* trans_w        = (const float*)d_in[11];
    const float* s1             = (const float*)d_in[12];
    const float* s2             = (const float*)d_in[13];

    int B  = in_sizes[3];
    int NU = in_sizes[4] / USER_DIM;
    float* out = (float*)d_out;

    const int k1_smem = (2*768*20 + 2*32*20 + GB*NSUM_LD + GB*40) * 4
                      + (GB*2*NSLOT + GB) * 4;
    cudaFuncSetAttribute(k1_kernel, cudaFuncAttributeMaxDynamicSharedMemorySize, k1_smem);

    k_scan<<<1, 1024>>>(indices, B, NU);

    k1_kernel<<<(B + GB - 1) / GB, 512, k1_smem>>>(
        train_types, node_neigh, neigh_features, tweet_u, user_u, s1, s2, B);

    int gtiles = (B + GBM - 1) / GBM;
    k_gemm2<<<2 * gtiles, GTH>>>(out, indices, user_features, text_features,
                                 user_embed, text_embed, trans_w, B, NU);
}